// round 12
// baseline (speedup 1.0000x reference)
#include <cuda_runtime.h>

#define NEGV -1000000000.0f

// Output layout (float offsets), reference return order:
// fwd_ts, fwd_ms, log_alpha, edge_log_alpha, log_betas, elb, ent, edge_ent
constexpr size_t O_FWD_TS    = 0;
constexpr size_t O_FWD_MS    = 131072;
constexpr size_t O_LOG_ALPHA = 262144;
constexpr size_t O_EDGE_LA   = 262208;
constexpr size_t O_LOG_BETAS = 393280;
constexpr size_t O_ELB       = 401472;
constexpr size_t O_ENT       = 17178688;
constexpr size_t O_EDGE_ENT  = 17178752;

// Backward staging (16-col chunks): PS%32==1, RS%8==2 -> STS conflict-free.
constexpr int RS    = 18;
constexpr int PS    = 16 * RS + 1;   // 289
constexpr int STAGE = 8 * PS;        // 2312 floats / warp

// Forward staging (8-col chunks): PS8%32==1, RS8%8==2 -> conflict-free.
constexpr int RS8    = 10;
constexpr int PS8    = 16 * RS8 + 1; // 161
constexpr int STAGE8 = 8 * PS8;      // 1288 floats per array

constexpr int SH_FLOATS = 2048 + 4 * STAGE;   // 11296 floats = 45184 B

// max-first LSE reduce: 4 MUFU exps (no rescale exp).
__device__ __forceinline__ void lse_reduce4(float a0, float a1, float a2, float a3,
                                            float& M, float& S) {
    float mx = fmaxf(fmaxf(a0, a1), fmaxf(a2, a3));
    mx = fmaxf(mx, __shfl_xor_sync(0xffffffffu, mx, 1));
    mx = fmaxf(mx, __shfl_xor_sync(0xffffffffu, mx, 2));
    float s = (__expf(a0 - mx) + __expf(a1 - mx)) +
              (__expf(a2 - mx) + __expf(a3 - mx));
    s += __shfl_xor_sync(0xffffffffu, s, 1);
    s += __shfl_xor_sync(0xffffffffu, s, 2);
    M = mx; S = s;
}

// 128-thread blocks (4 warps -> all 4 SMSPs). 4 lanes/problem, 4 rows/lane.
//  blockIdx.y < 4 : backward. b=blockIdx.x; warp w takes j-octet
//                   {y, 7-y, 8+y, 15-y}[w]  (balanced per block).
//  blockIdx.y == 4: forward+entropy. blockIdx.x < 2; warp w: 8 b's.
__global__ void __launch_bounds__(128)
tok_kernel(const float* __restrict__ fwd_ts,
           const float* __restrict__ bwd_ts,
           const int*   __restrict__ lengths,
           float* __restrict__ out)
{
    __shared__ float sh[SH_FLOATS];

    const int tid  = threadIdx.x;
    const int lane = tid & 31;
    const int w    = tid >> 5;
    const int l    = lane & 3;      // lane within 4-lane group
    const int p    = lane >> 2;     // problem within warp (0..7)
    const int rk0  = l * 4;         // first row of this lane

    if (blockIdx.y < 4) {
        // =================== backward scans ===================
        const int b   = blockIdx.x;
        const int len = lengths[b];
        const int y   = blockIdx.y;
        // balanced octet map: {y, 7-y, 8+y, 15-y}
        const int octet = (w & 1) ? ((w & 2) ? 15 - y : 7 - y)
                                  : ((w & 2) ? 8 + y : y);
        const int j0w = octet * 8;
        const int j   = j0w + p;
        const int i0  = 127 - j;

        const float* g = bwd_ts + (size_t)b * 2048;
        for (int x = tid; x < 2048; x += 128)
            sh[(x & 127) * 16 + (x >> 7)] = g[x];
        __syncthreads();

        float* stageW = sh + 2048 + w * STAGE;
        float* stp    = stageW + p * PS + rk0 * RS;
        float* elbW   = out + O_ELB + (size_t)(b * 128 + j0w) * 2048;

        const int start = 120 - j0w;        // all cols < start trivial
        const int cb0   = start & ~15;      // chunk-aligned bulk-skip boundary

        const int thr0 = i0 + rk0, thr1 = thr0 + 1, thr2 = thr0 + 2, thr3 = thr0 + 3;

        // ---- pipeline state, primed at column `start` (all prior la == 0) ----
        float la = 0.f, lb = 0.f;
        float w0 = 0.f, w1 = 0.f, w2 = 0.f, w3 = 0.f, svp = 0.f;
        float Qm, Qs, Q2m, Q2s, y1v;
        float cur0, cur1, cur2, cur3, nxt0, nxt1, nxt2, nxt3;
        float4 t4c, t4m;
        {
            t4c = *(const float4*)&sh[start * 16 + rk0];
            t4m = *(const float4*)&sh[min(start + 1, 127) * 16 + rk0];
            cur0 = (start >= thr0) ? t4c.x : NEGV;
            cur1 = (start >= thr1) ? t4c.y : NEGV;
            cur2 = (start >= thr2) ? t4c.z : NEGV;
            cur3 = (start >= thr3) ? t4c.w : NEGV;
            nxt0 = (start + 1 >= thr0) ? t4m.x : NEGV;
            nxt1 = (start + 1 >= thr1) ? t4m.y : NEGV;
            nxt2 = (start + 1 >= thr2) ? t4m.z : NEGV;
            nxt3 = (start + 1 >= thr3) ? t4m.w : NEGV;
            lse_reduce4((l > 0) ? cur0 : NEGV, (l > 0) ? cur1 : NEGV,
                        cur2, cur3, Qm, Qs);         // rows>=2, col start
            lse_reduce4((l > 0) ? nxt0 : NEGV, (l > 0) ? nxt1 : NEGV,
                        nxt2, nxt3, Q2m, Q2s);       // rows>=2, col start+1
            y1v = (start >= i0 + 1) ? t4c.y : NEGV;  // row1, col start (la=0)
        }

        const int q    = lane & 3;    // flush: float4 slot (16 cols)
        const int rsub = lane >> 2;   // flush: row sub-index (0..7)

        for (int cb = 0; cb < 128; cb += 16) {
            if (cb < cb0) {   // fully-trivial chunk: bulk NEG fill
                const float4 n4 = make_float4(NEGV, NEGV, NEGV, NEGV);
#pragma unroll 8
                for (int t = 0; t < 16; ++t) {
                    const int gg = t * 8 + rsub;
                    *(float4*)&elbW[(size_t)gg * 128 + cb + q * 4] = n4;
                }
                continue;
            }
#pragma unroll 2
            for (int cc = 0; cc < 16; ++cc) {
                const int c = cb + cc;
                if (c < start) {          // warp-uniform trivial column
                    stp[cc]          = NEGV;
                    stp[RS + cc]     = NEGV;
                    stp[2 * RS + cc] = NEGV;
                    stp[3 * RS + cc] = NEGV;
                } else if (c < len) {     // live step (uniform branch)
                    // -- off-chain: reduce rows>=2 of col c+2
                    const int cx = c + 2;
                    const float4 X = *(const float4*)&sh[min(cx, 127) * 16 + rk0];
                    const float sv = __shfl_up_sync(0xffffffffu, w2, 1);
                    const float p0 = (l > 0 && cx >= thr0) ? X.x + sv  : NEGV;
                    const float p1 = (l > 0 && cx >= thr1) ? X.y + svp : NEGV;
                    const float p2 = (cx >= thr2) ? X.z + w0 : NEGV;
                    const float p3 = (cx >= thr3) ? X.w + w1 : NEGV;
                    float Q3m, Q3s;
                    lse_reduce4(p0, p1, p2, p3, Q3m, Q3s);
                    // -- off-chain: row1 of col c+1 (uses la(c-1))
                    const float y2 = (c >= i0) ? t4m.y + la : NEGV;
                    // -- ON-CHAIN 3-term combine for col c
                    const float c0 = ((c >= i0) ? t4c.x : 0.f) + la;
                    const float mx = fmaxf(fmaxf(Qm, y1v), c0);
                    const float s  = Qs * __expf(Qm - mx) + __expf(y1v - mx)
                                   + __expf(c0 - mx);
                    const float laN = mx + __logf(s);
                    lb = (c == len - 1) ? laN : lb;
                    // -- emission col c (pipeline registers, pre-masked)
                    stp[cc]          = (l == 0) ? ((c >= i0) ? c0 : NEGV) : cur0;
                    stp[RS + cc]     = (l == 0) ? y1v : cur1;
                    stp[2 * RS + cc] = cur2;
                    stp[3 * RS + cc] = cur3;
                    // -- rotate
                    w3 = w2; w2 = w1; w1 = w0;
                    w0 = (l == 0) ? laN : svp;
                    la = laN;
                    Qm = Q2m; Qs = Q2s; Q2m = Q3m; Q2s = Q3s;
                    y1v = y2;
                    cur0 = nxt0; cur1 = nxt1; cur2 = nxt2; cur3 = nxt3;
                    nxt0 = p0; nxt1 = p1; nxt2 = p2; nxt3 = p3;
                    t4c = t4m; t4m = X;
                    svp = sv;
                } else {
                    // tail: cand = t + NEG where emask, else NEG
                    const float4 T = *(const float4*)&sh[c * 16 + rk0];
                    stp[cc]          = (c >= thr0) ? T.x + NEGV : NEGV;
                    stp[RS + cc]     = (c >= thr1) ? T.y + NEGV : NEGV;
                    stp[2 * RS + cc] = (c >= thr2) ? T.z + NEGV : NEGV;
                    stp[3 * RS + cc] = (c >= thr3) ? T.w + NEGV : NEGV;
                }
            }
            __syncwarp();
            // coalesced flush: 16 iterations, 8 rows x 64B each
#pragma unroll 4
            for (int t = 0; t < 16; ++t) {
                const int gg = t * 8 + rsub;
                const int pp = gg >> 4, rr = gg & 15;
                const float* s2 = stageW + pp * PS + rr * RS + q * 4;
                const float4 v = make_float4(s2[0], s2[1], s2[2], s2[3]);
                *(float4*)&elbW[(size_t)gg * 128 + cb + q * 4] = v;
            }
            __syncwarp();
        }
        if (l == 0)
            out[O_LOG_BETAS + (size_t)b * 128 + j] = lb;

    } else {
        // ====== forward + entropy (R10's 4-warp version, proven math) ======
        if (blockIdx.x >= 2) return;
        const int b   = (int)blockIdx.x * 32 + w * 8 + p;
        const int len = lengths[b];

        const float* tr = fwd_ts + (size_t)b * 2048 + (size_t)rk0 * 128;
        float* stLA = sh + w * (2 * STAGE8);
        float* stH  = stLA + STAGE8;
        float* elaW  = out + O_EDGE_LA  + (size_t)((int)blockIdx.x * 32 + w * 8) * 2048;
        float* eentW = out + O_EDGE_ENT + (size_t)((int)blockIdx.x * 32 + w * 8) * 2048;

        float w0 = 0.f, w1 = 0.f, w2 = 0.f, w3 = 0.f;
        float h0 = 0.f, h1 = 0.f, h2 = 0.f, h3 = 0.f;
        float laf = 0.f, hf = 0.f;
        float t0 = tr[0], t1 = tr[128], t2 = tr[256], t3 = tr[384];
        float* st  = stLA + p * PS8 + rk0 * RS8;
        float* sh2 = stH  + p * PS8 + rk0 * RS8;

        const int q2  = lane & 1;     // flush: float4 slot (8 cols)
        const int rs2 = lane >> 1;    // flush: row sub-index (0..15)

        for (int cb = 0; cb < 128; cb += 8) {
#pragma unroll 2
            for (int cc = 0; cc < 8; ++cc) {
                const int jj = cb + cc;
                float n0 = 0.f, n1 = 0.f, n2 = 0.f, n3 = 0.f;
                if (jj < 127) {   // prefetch next column (off-chain)
                    n0 = tr[jj + 1];       n1 = tr[128 + jj + 1];
                    n2 = tr[256 + jj + 1]; n3 = tr[384 + jj + 1];
                }
                const bool in = (jj < len);
                const bool m0 = in && (rk0     <= jj);
                const bool m1 = in && (rk0 + 1 <= jj);
                const bool m2 = in && (rk0 + 2 <= jj);
                const bool m3 = in && (rk0 + 3 <= jj);
                const float c0 = t0 + (m0 ? w0 : NEGV);
                const float c1 = t1 + (m1 ? w1 : NEGV);
                const float c2 = t2 + (m2 ? w2 : NEGV);
                const float c3 = t3 + (m3 ? w3 : NEGV);
                float mx = fmaxf(fmaxf(c0, c1), fmaxf(c2, c3));
                mx = fmaxf(mx, __shfl_xor_sync(0xffffffffu, mx, 1));
                mx = fmaxf(mx, __shfl_xor_sync(0xffffffffu, mx, 2));
                const float e0 = __expf(c0 - mx), e1 = __expf(c1 - mx);
                const float e2 = __expf(c2 - mx), e3 = __expf(c3 - mx);
                float ssr = (e0 + e1) + (e2 + e3);
                float ulr = (e0 * (h0 - c0) + e1 * (h1 - c1)) +
                            (e2 * (h2 - c2) + e3 * (h3 - c3));
                ssr += __shfl_xor_sync(0xffffffffu, ssr, 1);
                ulr += __shfl_xor_sync(0xffffffffu, ulr, 1);
                ssr += __shfl_xor_sync(0xffffffffu, ssr, 2);
                ulr += __shfl_xor_sync(0xffffffffu, ulr, 2);
                const float la  = mx + __logf(ssr);
                const float inv = __frcp_rn(ssr);
                const float hh  = in ? (la + ulr * inv) : 0.f;
                const float g0 = m0 ? (e0 * inv) * ((h0 + la) - c0) : 0.f;
                const float g1 = m1 ? (e1 * inv) * ((h1 + la) - c1) : 0.f;
                const float g2 = m2 ? (e2 * inv) * ((h2 + la) - c2) : 0.f;
                const float g3 = m3 ? (e3 * inv) * ((h3 + la) - c3) : 0.f;

                laf = (jj == len - 1) ? la : laf;
                hf  = (jj == len - 1) ? hh : hf;

                st[cc] = c0;  st[RS8 + cc] = c1;
                st[2 * RS8 + cc] = c2;  st[3 * RS8 + cc] = c3;
                sh2[cc] = g0; sh2[RS8 + cc] = g1;
                sh2[2 * RS8 + cc] = g2; sh2[3 * RS8 + cc] = g3;

                const float upw = __shfl_up_sync(0xffffffffu, w3, 1);
                const float uph = __shfl_up_sync(0xffffffffu, h3, 1);
                w3 = w2; w2 = w1; w1 = w0; w0 = (l == 0) ? la : upw;
                h3 = h2; h2 = h1; h1 = h0; h0 = (l == 0) ? hh : uph;
                t0 = n0; t1 = n1; t2 = n2; t3 = n3;
            }
            __syncwarp();
#pragma unroll 4
            for (int t = 0; t < 8; ++t) {
                const int gg = t * 16 + rs2;
                const int pp = gg >> 4, rr = gg & 15;
                const float* sA = stLA + pp * PS8 + rr * RS8 + q2 * 4;
                const float* sB = stH  + pp * PS8 + rr * RS8 + q2 * 4;
                const float4 vA = make_float4(sA[0], sA[1], sA[2], sA[3]);
                const float4 vB = make_float4(sB[0], sB[1], sB[2], sB[3]);
                *(float4*)&elaW [(size_t)gg * 128 + cb + q2 * 4] = vA;
                *(float4*)&eentW[(size_t)gg * 128 + cb + q2 * 4] = vB;
            }
            __syncwarp();
        }
        if (l == 0) {
            out[O_LOG_ALPHA + b] = laf;
            out[O_ENT + b]       = hf;
        }
    }
}

extern "C" void kernel_launch(void* const* d_in, const int* in_sizes, int n_in,
                              void* d_out, int out_size)
{
    const float* fwd_ts  = (const float*)d_in[0];
    const float* fwd_ms  = (const float*)d_in[1];
    const float* bwd_ts  = (const float*)d_in[2];
    const int*   lengths = (const int*)d_in[4];
    float* out = (float*)d_out;

    cudaMemcpyAsync(out + O_FWD_TS, fwd_ts, sizeof(float) * 131072,
                    cudaMemcpyDeviceToDevice);
    cudaMemcpyAsync(out + O_FWD_MS, fwd_ms, sizeof(float) * 131072,
                    cudaMemcpyDeviceToDevice);

    dim3 grid(64, 5);
    tok_kernel<<<grid, 128>>>(fwd_ts, bwd_ts, lengths, out);
}

// round 13
// speedup vs baseline: 1.9050x; 1.9050x over previous
#include <cuda_runtime.h>

#define NEGV -1000000000.0f

// Output layout (float offsets), reference return order:
// fwd_ts, fwd_ms, log_alpha, edge_log_alpha, log_betas, elb, ent, edge_ent
constexpr size_t O_FWD_TS    = 0;
constexpr size_t O_FWD_MS    = 131072;
constexpr size_t O_LOG_ALPHA = 262144;
constexpr size_t O_EDGE_LA   = 262208;
constexpr size_t O_LOG_BETAS = 393280;
constexpr size_t O_ELB       = 401472;
constexpr size_t O_ENT       = 17178688;
constexpr size_t O_EDGE_ENT  = 17178752;

// Staging strides (floats): PS%32==1, RS%8==2 -> compute-side STS conflict-free.
constexpr int RS    = 34;
constexpr int PS    = 16 * RS + 1;   // 545
constexpr int STAGE = 8 * PS;        // 4360 floats / warp

__device__ __forceinline__ void lse_reduce4(float a0, float a1, float a2, float a3,
                                            float& M, float& S) {
    float mx = fmaxf(fmaxf(a0, a1), fmaxf(a2, a3));
    float s = (__expf(a0 - mx) + __expf(a1 - mx)) +
              (__expf(a2 - mx) + __expf(a3 - mx));
    float Mt = fmaxf(mx, __shfl_xor_sync(0xffffffffu, mx, 1));
    Mt = fmaxf(Mt, __shfl_xor_sync(0xffffffffu, Mt, 2));
    float sg = s * __expf(mx - Mt);
    sg += __shfl_xor_sync(0xffffffffu, sg, 1);
    sg += __shfl_xor_sync(0xffffffffu, sg, 2);
    M = Mt; S = sg;
}

// 64-thread blocks (2 warps), 4 lanes/problem, 4 rows/lane.  [R11 proven]
//  blockIdx.y < 8 : backward, deep-pipelined. warp w: j = y*16 + w*8 + p.
//  blockIdx.y == 8: forward+entropy. blockIdx.x < 8, warp 0, b = x*8 + p.
__global__ void __launch_bounds__(64)
tok_kernel(const float* __restrict__ fwd_ts,
           const float* __restrict__ bwd_ts,
           const int*   __restrict__ lengths,
           float* __restrict__ out)
{
    __shared__ float sh[2048 + 2 * STAGE];   // 43072 B

    const int tid  = threadIdx.x;
    const int lane = tid & 31;
    const int w    = tid >> 5;
    const int l    = lane & 3;      // lane within 4-lane group
    const int p    = lane >> 2;     // problem within warp (0..7)
    const int rk0  = l * 4;         // first row of this lane
    const int q    = lane & 7;      // flush: float4 slot
    const int rsub = lane >> 3;     // flush: row sub-index

    if (blockIdx.y < 8) {
        // =================== backward scans ===================
        const int b   = blockIdx.x;
        const int len = lengths[b];
        const int j0w = (int)blockIdx.y * 16 + w * 8;
        const int j   = j0w + p;
        const int i0  = 127 - j;

        const float* g = bwd_ts + (size_t)b * 2048;
        for (int x = tid; x < 2048; x += 64)
            sh[(x & 127) * 16 + (x >> 7)] = g[x];
        __syncthreads();

        float* stageW = sh + 2048 + w * STAGE;
        float* stp    = stageW + p * PS + rk0 * RS;
        float* elbW   = out + O_ELB + (size_t)(b * 128 + j0w) * 2048;

        const int start = 120 - j0w;        // warp-min i0: all cols < start trivial
        const int cb0   = start & ~31;      // chunk-aligned bulk-skip boundary

        // live-row thresholds: row rk0+k live at col c iff c >= thr_k
        const int thr0 = i0 + rk0, thr1 = thr0 + 1, thr2 = thr0 + 2, thr3 = thr0 + 3;

        // ---- pipeline state, primed at column `start` (all prior la == 0) ----
        float la = 0.f, lb = 0.f;
        float w0 = 0.f, w1 = 0.f, w2 = 0.f, w3 = 0.f, svp = 0.f;
        float Qm, Qs, Q2m, Q2s, y1v;
        float cur0, cur1, cur2, cur3, nxt0, nxt1, nxt2, nxt3;
        float4 t4c, t4m;
        {
            t4c = *(const float4*)&sh[start * 16 + rk0];
            t4m = *(const float4*)&sh[min(start + 1, 127) * 16 + rk0];
            cur0 = (start >= thr0) ? t4c.x : NEGV;   // + la(..)=0
            cur1 = (start >= thr1) ? t4c.y : NEGV;
            cur2 = (start >= thr2) ? t4c.z : NEGV;
            cur3 = (start >= thr3) ? t4c.w : NEGV;
            nxt0 = (start + 1 >= thr0) ? t4m.x : NEGV;
            nxt1 = (start + 1 >= thr1) ? t4m.y : NEGV;
            nxt2 = (start + 1 >= thr2) ? t4m.z : NEGV;
            nxt3 = (start + 1 >= thr3) ? t4m.w : NEGV;
            lse_reduce4((l > 0) ? cur0 : NEGV, (l > 0) ? cur1 : NEGV,
                        cur2, cur3, Qm, Qs);         // rows>=2, col start
            lse_reduce4((l > 0) ? nxt0 : NEGV, (l > 0) ? nxt1 : NEGV,
                        nxt2, nxt3, Q2m, Q2s);       // rows>=2, col start+1
            y1v = (start >= i0 + 1) ? t4c.y : NEGV;  // row1, col start (la=0)
        }

        for (int cb = 0; cb < 128; cb += 32) {
            if (cb < cb0) {   // fully-trivial chunk: bulk NEG fill
                const float4 n4 = make_float4(NEGV, NEGV, NEGV, NEGV);
#pragma unroll 8
                for (int t = 0; t < 32; ++t) {
                    const int gg = t * 4 + rsub;
                    *(float4*)&elbW[(size_t)gg * 128 + cb + q * 4] = n4;
                }
                continue;
            }
#pragma unroll 2
            for (int cc = 0; cc < 32; ++cc) {
                const int c = cb + cc;
                if (c < start) {          // warp-uniform trivial column
                    stp[cc]          = NEGV;
                    stp[RS + cc]     = NEGV;
                    stp[2 * RS + cc] = NEGV;
                    stp[3 * RS + cc] = NEGV;
                } else if (c < len) {     // live step (uniform branch)
                    // -- off-chain: reduce rows>=2 of col c+2
                    const int cx = c + 2;
                    const float4 X = *(const float4*)&sh[min(cx, 127) * 16 + rk0];
                    const float sv = __shfl_up_sync(0xffffffffu, w2, 1);
                    const float p0 = (l > 0 && cx >= thr0) ? X.x + sv  : NEGV;
                    const float p1 = (l > 0 && cx >= thr1) ? X.y + svp : NEGV;
                    const float p2 = (cx >= thr2) ? X.z + w0 : NEGV;
                    const float p3 = (cx >= thr3) ? X.w + w1 : NEGV;
                    float Q3m, Q3s;
                    lse_reduce4(p0, p1, p2, p3, Q3m, Q3s);
                    // -- off-chain: row1 of col c+1 (uses la(c-1))
                    const float y2 = (c >= i0) ? t4m.y + la : NEGV;
                    // -- ON-CHAIN 3-term combine for col c
                    const float c0 = ((c >= i0) ? t4c.x : 0.f) + la;
                    const float mx = fmaxf(fmaxf(Qm, y1v), c0);
                    const float s  = Qs * __expf(Qm - mx) + __expf(y1v - mx)
                                   + __expf(c0 - mx);
                    const float laN = mx + __logf(s);
                    lb = (c == len - 1) ? laN : lb;
                    // -- emission col c (pipeline registers, pre-masked)
                    stp[cc]          = (l == 0) ? ((c >= i0) ? c0 : NEGV) : cur0;
                    stp[RS + cc]     = (l == 0) ? y1v : cur1;
                    stp[2 * RS + cc] = cur2;
                    stp[3 * RS + cc] = cur3;
                    // -- rotate
                    w3 = w2; w2 = w1; w1 = w0;
                    w0 = (l == 0) ? laN : svp;
                    la = laN;
                    Qm = Q2m; Qs = Q2s; Q2m = Q3m; Q2s = Q3s;
                    y1v = y2;
                    cur0 = nxt0; cur1 = nxt1; cur2 = nxt2; cur3 = nxt3;
                    nxt0 = p0; nxt1 = p1; nxt2 = p2; nxt3 = p3;
                    t4c = t4m; t4m = X;
                    svp = sv;
                } else {
                    // tail: cand = t + NEG where emask, else NEG
                    const float4 T = *(const float4*)&sh[c * 16 + rk0];
                    stp[cc]          = (c >= thr0) ? T.x + NEGV : NEGV;
                    stp[RS + cc]     = (c >= thr1) ? T.y + NEGV : NEGV;
                    stp[2 * RS + cc] = (c >= thr2) ? T.z + NEGV : NEGV;
                    stp[3 * RS + cc] = (c >= thr3) ? T.w + NEGV : NEGV;
                }
            }
            __syncwarp();
#pragma unroll 4
            for (int t = 0; t < 32; ++t) {
                const int gg = t * 4 + rsub;
                const int pp = gg >> 4, rr = gg & 15;
                const float* s2 = stageW + pp * PS + rr * RS + q * 4;
                const float4 v = make_float4(s2[0], s2[1], s2[2], s2[3]);
                *(float4*)&elbW[(size_t)gg * 128 + cb + q * 4] = v;
            }
            __syncwarp();
        }
        if (l == 0)
            out[O_LOG_BETAS + (size_t)b * 128 + j] = lb;

    } else {
        // ===== forward + entropy (byte-identical to the 47.2us version) =====
        if (blockIdx.x >= 8 || w != 0) return;
        const int b   = (int)blockIdx.x * 8 + p;
        const int len = lengths[b];

        const float* tr = fwd_ts + (size_t)b * 2048 + (size_t)rk0 * 128;
        float* stLA = sh;
        float* stH  = sh + STAGE;
        float* elaW  = out + O_EDGE_LA  + (size_t)blockIdx.x * 8 * 2048;
        float* eentW = out + O_EDGE_ENT + (size_t)blockIdx.x * 8 * 2048;

        float w0 = 0.f, w1 = 0.f, w2 = 0.f, w3 = 0.f;
        float h0 = 0.f, h1 = 0.f, h2 = 0.f, h3 = 0.f;
        float laf = 0.f, hf = 0.f;
        float t0 = tr[0], t1 = tr[128], t2 = tr[256], t3 = tr[384];
        float* st = stLA + p * PS + rk0 * RS;
        float* sh2 = stH + p * PS + rk0 * RS;

        for (int cb = 0; cb < 128; cb += 32) {
#pragma unroll 2
            for (int cc = 0; cc < 32; ++cc) {
                const int jj = cb + cc;
                float n0 = 0.f, n1 = 0.f, n2 = 0.f, n3 = 0.f;
                if (jj < 127) {   // prefetch next column (off-chain)
                    n0 = tr[jj + 1];       n1 = tr[128 + jj + 1];
                    n2 = tr[256 + jj + 1]; n3 = tr[384 + jj + 1];
                }
                const bool in = (jj < len);
                const bool m0 = in && (rk0     <= jj);
                const bool m1 = in && (rk0 + 1 <= jj);
                const bool m2 = in && (rk0 + 2 <= jj);
                const bool m3 = in && (rk0 + 3 <= jj);
                const float c0 = t0 + (m0 ? w0 : NEGV);
                const float c1 = t1 + (m1 ? w1 : NEGV);
                const float c2 = t2 + (m2 ? w2 : NEGV);
                const float c3 = t3 + (m3 ? w3 : NEGV);
                float mx = fmaxf(fmaxf(c0, c1), fmaxf(c2, c3));
                mx = fmaxf(mx, __shfl_xor_sync(0xffffffffu, mx, 1));
                mx = fmaxf(mx, __shfl_xor_sync(0xffffffffu, mx, 2));
                const float e0 = __expf(c0 - mx), e1 = __expf(c1 - mx);
                const float e2 = __expf(c2 - mx), e3 = __expf(c3 - mx);
                float ssr = (e0 + e1) + (e2 + e3);
                float ulr = (e0 * (h0 - c0) + e1 * (h1 - c1)) +
                            (e2 * (h2 - c2) + e3 * (h3 - c3));
                ssr += __shfl_xor_sync(0xffffffffu, ssr, 1);
                ulr += __shfl_xor_sync(0xffffffffu, ulr, 1);
                ssr += __shfl_xor_sync(0xffffffffu, ssr, 2);
                ulr += __shfl_xor_sync(0xffffffffu, ulr, 2);
                const float la  = mx + __logf(ssr);
                const float inv = __frcp_rn(ssr);
                const float hh  = in ? (la + ulr * inv) : 0.f;
                const float g0 = m0 ? (e0 * inv) * ((h0 + la) - c0) : 0.f;
                const float g1 = m1 ? (e1 * inv) * ((h1 + la) - c1) : 0.f;
                const float g2 = m2 ? (e2 * inv) * ((h2 + la) - c2) : 0.f;
                const float g3 = m3 ? (e3 * inv) * ((h3 + la) - c3) : 0.f;

                laf = (jj == len - 1) ? la : laf;
                hf  = (jj == len - 1) ? hh : hf;

                st[cc] = c0;  st[RS + cc] = c1;  st[2 * RS + cc] = c2;  st[3 * RS + cc] = c3;
                sh2[cc] = g0; sh2[RS + cc] = g1; sh2[2 * RS + cc] = g2; sh2[3 * RS + cc] = g3;

                const float upw = __shfl_up_sync(0xffffffffu, w3, 1);
                const float uph = __shfl_up_sync(0xffffffffu, h3, 1);
                w3 = w2; w2 = w1; w1 = w0; w0 = (l == 0) ? la : upw;
                h3 = h2; h2 = h1; h1 = h0; h0 = (l == 0) ? hh : uph;
                t0 = n0; t1 = n1; t2 = n2; t3 = n3;
            }
            __syncwarp();
#pragma unroll 4
            for (int t = 0; t < 32; ++t) {
                const int gg = t * 4 + rsub;
                const int pp = gg >> 4, rr = gg & 15;
                const float* sA = stLA + pp * PS + rr * RS + q * 4;
                const float* sB = stH  + pp * PS + rr * RS + q * 4;
                const float4 vA = make_float4(sA[0], sA[1], sA[2], sA[3]);
                const float4 vB = make_float4(sB[0], sB[1], sB[2], sB[3]);
                *(float4*)&elaW [(size_t)gg * 128 + cb + q * 4] = vA;
                *(float4*)&eentW[(size_t)gg * 128 + cb + q * 4] = vB;
            }
            __syncwarp();
        }
        if (l == 0) {
            out[O_LOG_ALPHA + b] = laf;
            out[O_ENT + b]       = hf;
        }
    }
}

extern "C" void kernel_launch(void* const* d_in, const int* in_sizes, int n_in,
                              void* d_out, int out_size)
{
    const float* fwd_ts  = (const float*)d_in[0];
    const float* fwd_ms  = (const float*)d_in[1];
    const float* bwd_ts  = (const float*)d_in[2];
    const int*   lengths = (const int*)d_in[4];
    float* out = (float*)d_out;

    // Raise the shared-memory carveout so >2 blocks (43KB each) fit per SM.
    // Host-side attribute set: not a stream op, not an allocation -> capture-safe.
    cudaFuncSetAttribute(tok_kernel,
                         cudaFuncAttributePreferredSharedMemoryCarveout,
                         cudaSharedmemCarveoutMaxShared);

    cudaMemcpyAsync(out + O_FWD_TS, fwd_ts, sizeof(float) * 131072,
                    cudaMemcpyDeviceToDevice);
    cudaMemcpyAsync(out + O_FWD_MS, fwd_ms, sizeof(float) * 131072,
                    cudaMemcpyDeviceToDevice);

    dim3 grid(64, 9);
    tok_kernel<<<grid, 64>>>(fwd_ts, bwd_ts, lengths, out);
}